// round 13
// baseline (speedup 1.0000x reference)
#include <cuda_runtime.h>
#include <cuda.h>
#include <cstdint>

// Causal unbiased-EMA instance norm, x: [B=8, C=256, T=16384] fp32 — EXACT
// via per-lane affine prefix scan, warp-autonomous dataflow (R12) + TMA
// tile load/store with SW128 swizzle (R13).
//
//   s1 = a*s1 + (1-a)*x ; s2 = a*s2 + (1-a)*x^2 ; w = a*w + (1-a)  (= 1-a^t)
//   y  = (w*x - s1) * rsqrt(w*s2 + eps*w^2 - s1^2)   [floored at 1e-10]
//
// TMA path (preferred): one block per lane, 512 threads, KP=32 (rows of
// 128B). Each warp owns a 32-row (4KB) tile: 1 TMA load -> pass1 -> warp
// scan -> flag-relay cross-warp prefix -> pass2 in place -> 1 TMA store.
// SW128 swizzle makes the per-thread row sweep bank-conflict-free.
// Fallback path: the R12 cp.async kernel (used if the tensormap encoder
// entry point is unavailable).

#define ALPHA_F 0.99f
#define OMA_F   0.01f
#define EPS_F   1e-5f

__host__ __device__ constexpr float apow(int n) {
    float r = 1.0f;
    for (int i = 0; i < n; i++) r *= ALPHA_F;
    return r;
}

__device__ __forceinline__ uint32_t smem_u32(const void* p) {
    return (uint32_t)__cvta_generic_to_shared(p);
}

// full step: w still evolving (also exact once w saturates to 1.0f)
__device__ __forceinline__ float ema_step_w(float xi, float& s1, float& s2, float& w) {
    float t = OMA_F * xi;
    s1 = fmaf(ALPHA_F, s1, t);
    s2 = fmaf(ALPHA_F, s2, t * xi);
    w  = fmaf(ALPHA_F, w, OMA_F);
    float num = fmaf(w, xi, -s1);
    float e   = fmaf(EPS_F, w, s2);
    float d   = fmaf(w, e, -(s1 * s1));
    d = fmaxf(d, 1e-10f);
    float r;
    asm("rsqrt.approx.f32 %0, %1;" : "=f"(r) : "f"(d));
    return num * r;
}

// saturated step: w == 1.0f exactly (t0 >= 1792)
__device__ __forceinline__ float ema_step_1(float xi, float& s1, float& s2) {
    float t = OMA_F * xi;
    s1 = fmaf(ALPHA_F, s1, t);
    s2 = fmaf(ALPHA_F, s2, t * xi);
    float num = xi - s1;
    float e   = s2 + EPS_F;
    float d   = fmaf(-s1, s1, e);
    d = fmaxf(d, 1e-10f);
    float r;
    asm("rsqrt.approx.f32 %0, %1;" : "=f"(r) : "f"(d));
    return num * r;
}

// ======================= TMA kernel (TPB=512, KP=32) =======================

#define T_LEN   16384
#define TPB_T   512
#define KP_T    32
#define NW_T    16
#define A32_F   0.72498034f   // 0.99^32

// pass-1 dot product over a swizzled 128B row; compile-time weights.
template<int I>
__device__ __forceinline__ void warm32(const char* rowbase, int sw,
                                       float& a0, float& b0, float& a1, float& b1) {
    if constexpr (I < 8) {
        float4 v = *reinterpret_cast<const float4*>(rowbase + ((I * 16) ^ sw));
        constexpr float c0 = OMA_F * apow(KP_T - 1 - (4 * I + 0));
        constexpr float c1 = OMA_F * apow(KP_T - 1 - (4 * I + 1));
        constexpr float c2 = OMA_F * apow(KP_T - 1 - (4 * I + 2));
        constexpr float c3 = OMA_F * apow(KP_T - 1 - (4 * I + 3));
        float t0 = c0 * v.x;  a0 += t0;  b0 = fmaf(t0, v.x, b0);
        float t1 = c1 * v.y;  a1 += t1;  b1 = fmaf(t1, v.y, b1);
        float t2 = c2 * v.z;  a0 += t2;  b0 = fmaf(t2, v.z, b0);
        float t3 = c3 * v.w;  a1 += t3;  b1 = fmaf(t3, v.w, b1);
        warm32<I + 1>(rowbase, sw, a0, b0, a1, b1);
    }
}

// smem: [align slack 1024][tiles 64KB][mbar 16*8][pub1/2/m 48*4][flag 16*4]
#define SMEM_TMA 67072

__global__ void __launch_bounds__(TPB_T)
ema_tma_kernel(const __grid_constant__ CUtensorMap tmx,
               const __grid_constant__ CUtensorMap tmy)
{
    extern __shared__ __align__(16) char s_raw[];
    uintptr_t ab = ((uintptr_t)s_raw + 1023) & ~(uintptr_t)1023;
    char*           tiles = (char*)ab;                              // 64 KB
    uint64_t*       mbar  = (uint64_t*)(tiles + 65536);             // 16
    volatile float* pub1  = (volatile float*)(tiles + 65536 + 128);
    volatile float* pub2  = pub1 + NW_T;
    volatile float* pubm  = pub2 + NW_T;
    volatile int*   flag  = (volatile int*)(pubm + NW_T);

    const int tid  = threadIdx.x;
    const int lane = tid & 31;
    const int wid  = tid >> 5;

    // per-launch init (graph replays leave stale smem)
    if (lane == 0) {
        uint32_t mb = smem_u32(mbar + wid);
        asm volatile("mbarrier.init.shared.b64 [%0], 1;" :: "r"(mb) : "memory");
    }
    if (tid < NW_T) flag[tid] = 0;
    __syncthreads();                       // only block-wide barrier

    char* wtile = tiles + wid * 4096;      // 1024B aligned -> SW128 valid
    const int row_g = blockIdx.x * (T_LEN / KP_T) + wid * 32;
    uint32_t mb = smem_u32(mbar + wid);

    if (lane == 0) {
        asm volatile("mbarrier.arrive.expect_tx.shared.b64 _, [%0], 4096;"
                     :: "r"(mb) : "memory");
        asm volatile("cp.async.bulk.tensor.2d.shared::cta.global.tile.mbarrier::complete_tx::bytes "
                     "[%0], [%1, {%2, %3}], [%4];"
                     :: "r"(smem_u32(wtile)), "l"(&tmx), "r"(0), "r"(row_g), "r"(mb)
                     : "memory");
    }
    // wait parity 0 (fresh mbarrier every launch)
    asm volatile("{\n\t.reg .pred p;\nWL%=:\n\t"
                 "mbarrier.try_wait.parity.shared.b64 p, [%0], 0;\n\t"
                 "@!p bra WL%=;\n\t}"
                 :: "r"(mb) : "memory");
    __syncwarp();
    if (lane == 0)
        asm volatile("mbarrier.inval.shared.b64 [%0];" :: "r"(mb) : "memory");

    // ---- pass 1: constant-weight row sums (swizzled LDS.128) ----
    const char* rowbase = wtile + lane * 128;
    const int sw = (lane & 7) * 16;
    float a0 = 0.f, b0 = 0.f, a1 = 0.f, b1 = 0.f;
    warm32<0>(rowbase, sw, a0, b0, a1, b1);
    float L1 = a0 + a1;
    float L2 = b0 + b1;

    // ---- in-warp affine inclusive scan: combine = vR + mR*vL ----
    float v1 = L1, v2 = L2, m = A32_F;
    #pragma unroll
    for (int d = 1; d < 32; d <<= 1) {
        float pv1 = __shfl_up_sync(0xffffffffu, v1, d);
        float pv2 = __shfl_up_sync(0xffffffffu, v2, d);
        float pm  = __shfl_up_sync(0xffffffffu, m,  d);
        if (lane >= d) {
            v1 = fmaf(m, pv1, v1);
            v2 = fmaf(m, pv2, v2);
            m *= pm;
        }
    }
    float ev1 = __shfl_up_sync(0xffffffffu, v1, 1);
    float ev2 = __shfl_up_sync(0xffffffffu, v2, 1);
    float em  = __shfl_up_sync(0xffffffffu, m,  1);
    if (lane == 0) { ev1 = 0.f; ev2 = 0.f; em = 1.f; }

    // ---- cross-warp prefix: flag-chained relay through smem ----
    float p1 = 0.f, p2 = 0.f, pm = 1.f;
    if (wid > 0) {
        if (lane == 0) { while (flag[wid - 1] == 0) {} }
        __syncwarp();
        __threadfence_block();
        p1 = pub1[wid - 1]; p2 = pub2[wid - 1]; pm = pubm[wid - 1];
    }
    if (wid < NW_T - 1 && lane == 31) {
        pub1[wid] = fmaf(m, p1, v1);
        pub2[wid] = fmaf(m, p2, v2);
        pubm[wid] = m * pm;
        __threadfence_block();
        flag[wid] = 1;
    }

    float s1 = fmaf(em, p1, ev1);
    float s2 = fmaf(em, p2, ev2);
    float w  = 1.0f - pm * em;             // == 1.0f exactly for t0 >= 1792

    // ---- pass 2: normalize 32 steps in place (swizzled, conflict-free) ----
    char* rwb = wtile + lane * 128;
    if (wid >= 2) {                        // t0 >= 2048 -> w saturated, warp-uniform
        #pragma unroll
        for (int i = 0; i < 8; i++) {
            float4* p = reinterpret_cast<float4*>(rwb + ((i * 16) ^ sw));
            float4 v = *p;
            float4 o;
            o.x = ema_step_1(v.x, s1, s2);
            o.y = ema_step_1(v.y, s1, s2);
            o.z = ema_step_1(v.z, s1, s2);
            o.w = ema_step_1(v.w, s1, s2);
            *p = o;
        }
    } else {
        #pragma unroll
        for (int i = 0; i < 8; i++) {
            float4* p = reinterpret_cast<float4*>(rwb + ((i * 16) ^ sw));
            float4 v = *p;
            float4 o;
            o.x = ema_step_w(v.x, s1, s2, w);
            o.y = ema_step_w(v.y, s1, s2, w);
            o.z = ema_step_w(v.z, s1, s2, w);
            o.w = ema_step_w(v.w, s1, s2, w);
            *p = o;
        }
    }
    __syncwarp();                          // warp tile fully written

    // ---- TMA store of this warp's tile (de-swizzles on the way out) ----
    if (lane == 0) {
        asm volatile("fence.proxy.async;" ::: "memory");
        asm volatile("cp.async.bulk.tensor.2d.global.shared::cta.tile.bulk_group "
                     "[%0, {%1, %2}], [%3];"
                     :: "l"(&tmy), "r"(0), "r"(row_g), "r"(smem_u32(wtile))
                     : "memory");
        asm volatile("cp.async.bulk.commit_group;");
        asm volatile("cp.async.bulk.wait_group 0;" ::: "memory");
    }
}

// ================== Fallback kernel (R12, cp.async path) ==================

#define TPB_F   256
#define KP_F    64
#define NW_F    8
#define WSEG_F  2048
#define A64_F   0.52559649f
#define W1_TID  28

#define PAD_F(i)  ((i) + (((i) >> 6) << 2))
#define SMEM_FB   ((T_LEN + ((T_LEN >> 6) << 2)) * 4)

__device__ __forceinline__ void cp_async16(float* smem_dst, const float* gmem_src) {
    uint32_t s = (uint32_t)__cvta_generic_to_shared(smem_dst);
    asm volatile("cp.async.cg.shared.global [%0], [%1], 16;" :: "r"(s), "l"(gmem_src));
}

template<int I>
__device__ __forceinline__ void warm64(const float4* row,
                                       float& a0, float& b0, float& a1, float& b1) {
    if constexpr (I < KP_F / 4) {
        float4 v = row[I];
        constexpr float c0 = OMA_F * apow(KP_F - 1 - (4 * I + 0));
        constexpr float c1 = OMA_F * apow(KP_F - 1 - (4 * I + 1));
        constexpr float c2 = OMA_F * apow(KP_F - 1 - (4 * I + 2));
        constexpr float c3 = OMA_F * apow(KP_F - 1 - (4 * I + 3));
        float t0 = c0 * v.x;  a0 += t0;  b0 = fmaf(t0, v.x, b0);
        float t1 = c1 * v.y;  a1 += t1;  b1 = fmaf(t1, v.y, b1);
        float t2 = c2 * v.z;  a0 += t2;  b0 = fmaf(t2, v.z, b0);
        float t3 = c3 * v.w;  a1 += t3;  b1 = fmaf(t3, v.w, b1);
        warm64<I + 1>(row, a0, b0, a1, b1);
    }
}

extern __shared__ float s_buf[];

__global__ void __launch_bounds__(TPB_F)
ema_fb_kernel(const float* __restrict__ x, float* __restrict__ y)
{
    __shared__ volatile float fpub1[NW_F], fpub2[NW_F], fpubm[NW_F];
    __shared__ volatile int   fflag[NW_F];

    const int tid  = threadIdx.x;
    const int lane = tid & 31;
    const int wid  = tid >> 5;
    const size_t base = (size_t)blockIdx.x * T_LEN;

    if (tid < NW_F) fflag[tid] = 0;
    __syncthreads();

    const int wbase = wid * WSEG_F;
    #pragma unroll
    for (int k = 0; k < WSEG_F / (32 * 4); k++) {
        int i4 = wbase + k * (32 * 4) + 4 * lane;
        cp_async16(s_buf + PAD_F(i4), x + base + i4);
    }
    asm volatile("cp.async.commit_group;");
    asm volatile("cp.async.wait_group 0;" ::: "memory");
    __syncwarp();

    const int t0 = tid * KP_F;
    const float4* row = reinterpret_cast<const float4*>(s_buf + PAD_F(t0));
    float a0 = 0.f, b0 = 0.f, a1 = 0.f, b1 = 0.f;
    warm64<0>(row, a0, b0, a1, b1);
    float L1 = a0 + a1, L2 = b0 + b1;

    float v1 = L1, v2 = L2, m = A64_F;
    #pragma unroll
    for (int d = 1; d < 32; d <<= 1) {
        float pv1 = __shfl_up_sync(0xffffffffu, v1, d);
        float pv2 = __shfl_up_sync(0xffffffffu, v2, d);
        float pm  = __shfl_up_sync(0xffffffffu, m,  d);
        if (lane >= d) {
            v1 = fmaf(m, pv1, v1);
            v2 = fmaf(m, pv2, v2);
            m *= pm;
        }
    }
    float ev1 = __shfl_up_sync(0xffffffffu, v1, 1);
    float ev2 = __shfl_up_sync(0xffffffffu, v2, 1);
    float em  = __shfl_up_sync(0xffffffffu, m,  1);
    if (lane == 0) { ev1 = 0.f; ev2 = 0.f; em = 1.f; }

    float p1 = 0.f, p2 = 0.f, pm = 1.f;
    if (wid > 0) {
        if (lane == 0) { while (fflag[wid - 1] == 0) {} }
        __syncwarp();
        __threadfence_block();
        p1 = fpub1[wid - 1]; p2 = fpub2[wid - 1]; pm = fpubm[wid - 1];
    }
    if (wid < NW_F - 1 && lane == 31) {
        fpub1[wid] = fmaf(m, p1, v1);
        fpub2[wid] = fmaf(m, p2, v2);
        fpubm[wid] = m * pm;
        __threadfence_block();
        fflag[wid] = 1;
    }

    float s1 = fmaf(em, p1, ev1);
    float s2 = fmaf(em, p2, ev2);
    float w  = 1.0f - pm * em;

    float4* rw = reinterpret_cast<float4*>(s_buf + PAD_F(t0));
    if (tid >= W1_TID) {
        #pragma unroll
        for (int i = 0; i < KP_F / 4; i++) {
            float4 v = rw[i];
            float4 o;
            o.x = ema_step_1(v.x, s1, s2);
            o.y = ema_step_1(v.y, s1, s2);
            o.z = ema_step_1(v.z, s1, s2);
            o.w = ema_step_1(v.w, s1, s2);
            rw[i] = o;
        }
    } else {
        #pragma unroll
        for (int i = 0; i < KP_F / 4; i++) {
            float4 v = rw[i];
            float4 o;
            o.x = ema_step_w(v.x, s1, s2, w);
            o.y = ema_step_w(v.y, s1, s2, w);
            o.z = ema_step_w(v.z, s1, s2, w);
            o.w = ema_step_w(v.w, s1, s2, w);
            rw[i] = o;
        }
    }
    __syncwarp();

    #pragma unroll
    for (int k = 0; k < WSEG_F / (32 * 4); k++) {
        int i4 = wbase + k * (32 * 4) + 4 * lane;
        float4 v = *reinterpret_cast<const float4*>(s_buf + PAD_F(i4));
        *reinterpret_cast<float4*>(y + base + i4) = v;
    }
}

// ============================== host launch ==============================

typedef CUresult (*EncodeTiledFn)(
    CUtensorMap*, CUtensorMapDataType, cuuint32_t, void*,
    const cuuint64_t*, const cuuint64_t*, const cuuint32_t*, const cuuint32_t*,
    CUtensorMapInterleave, CUtensorMapSwizzle, CUtensorMapL2promotion,
    CUtensorMapFloatOOBfill);

extern "C" void kernel_launch(void* const* d_in, const int* in_sizes, int n_in,
                              void* d_out, int out_size) {
    const float* x = (const float*)d_in[0];
    float*       y = (float*)d_out;

    int total = in_sizes[0];            // B*C*T
    int lanes = total / T_LEN;          // 2048

    void* fnp = nullptr;
    cudaDriverEntryPointQueryResult qr;
    cudaError_t e = cudaGetDriverEntryPoint("cuTensorMapEncodeTiled", &fnp,
                                            cudaEnableDefault, &qr);
    bool ok = (e == cudaSuccess) && fnp;

    CUtensorMap tmx{}, tmy{};
    if (ok) {
        EncodeTiledFn enc = (EncodeTiledFn)fnp;
        cuuint64_t dims[2]    = {32, (cuuint64_t)total / 32};
        cuuint64_t strides[1] = {128};               // 32 floats per row
        cuuint32_t box[2]     = {32, 32};            // 128B x 32 rows = 4KB
        cuuint32_t est[2]     = {1, 1};
        CUresult r1 = enc(&tmx, CU_TENSOR_MAP_DATA_TYPE_FLOAT32, 2, (void*)x,
                          dims, strides, box, est,
                          CU_TENSOR_MAP_INTERLEAVE_NONE, CU_TENSOR_MAP_SWIZZLE_128B,
                          CU_TENSOR_MAP_L2_PROMOTION_L2_128B,
                          CU_TENSOR_MAP_FLOAT_OOB_FILL_NONE);
        CUresult r2 = enc(&tmy, CU_TENSOR_MAP_DATA_TYPE_FLOAT32, 2, (void*)y,
                          dims, strides, box, est,
                          CU_TENSOR_MAP_INTERLEAVE_NONE, CU_TENSOR_MAP_SWIZZLE_128B,
                          CU_TENSOR_MAP_L2_PROMOTION_L2_128B,
                          CU_TENSOR_MAP_FLOAT_OOB_FILL_NONE);
        ok = (r1 == CUDA_SUCCESS) && (r2 == CUDA_SUCCESS);
    }

    if (ok) {
        cudaFuncSetAttribute(ema_tma_kernel,
                             cudaFuncAttributeMaxDynamicSharedMemorySize, SMEM_TMA);
        ema_tma_kernel<<<lanes, TPB_T, SMEM_TMA>>>(tmx, tmy);
    } else {
        cudaFuncSetAttribute(ema_fb_kernel,
                             cudaFuncAttributeMaxDynamicSharedMemorySize, SMEM_FB);
        ema_fb_kernel<<<lanes, TPB_F, SMEM_FB>>>(x, y);
    }
}